// round 10
// baseline (speedup 1.0000x reference)
#include <cuda_runtime.h>
#include <cstdint>

#define B_     2
#define R_     512
#define C_     256
#define H0_    256
#define H1_    128
#define NBOX_  (B_ * R_)            // 1024
#define NCELLB_ 49
#define THREADS_ 256                // thread t owns channel t

struct DescO { int x, y, z, w; };           // corner byte offsets
struct DescW { float w00, w01, w10, w11; }; // folded bilinear weights (validity folded)

__global__ __launch_bounds__(THREADS_) void roialign_kernel(
    const float* __restrict__ feat0,
    const float* __restrict__ feat1,
    const float* __restrict__ rois,
    float* __restrict__ out)
{
    __shared__ DescO cdo[NCELLB_];
    __shared__ DescW cdw[NCELLB_];
    __shared__ int s_lvl;

    int n = blockIdx.x;
    int t = threadIdx.x;

    if (t < NCELLB_) {
        const float* roi = rois + (size_t)n * 5;
        float y1 = roi[0], x1 = roi[1], y2 = roi[2], x2 = roi[3];
        bool lvl = ((y2 - y1) > 48.0f) || ((x2 - x1) > 48.0f);
        if (t == 0) s_lvl = lvl ? 1 : 0;
        int H = lvl ? H1_ : H0_;
        float Hm1 = (float)(H - 1);
        int b = n >> 9;

        const float inv = 1.0f / 1024.0f;
        float y1n = y1 * inv, x1n = x1 * inv, y2n = y2 * inv, x2n = x2 * inv;

        int py = t / 7;
        int px = t - py * 7;
        float ry = (float)py * (1.0f / 6.0f);
        float rx = (float)px * (1.0f / 6.0f);
        float ys = (y1n + ry * (y2n - y1n)) * Hm1;
        float xs = (x1n + rx * (x2n - x1n)) * Hm1;

        float validf = ((ys >= 0.0f) && (ys <= Hm1) && (xs >= 0.0f) && (xs <= Hm1))
                       ? 1.0f : 0.0f;

        float y0f = floorf(ys);
        float x0f = floorf(xs);
        float wy = ys - y0f;
        float wx = xs - x0f;
        int y0 = (int)fminf(fmaxf(y0f, 0.0f), Hm1);
        int x0 = (int)fminf(fmaxf(x0f, 0.0f), Hm1);
        int yp = min(y0 + 1, H - 1);
        int xp = min(x0 + 1, H - 1);

        int rowB = H * (C_ * 4);
        int baseB  = (b * H + y0) * rowB;
        int basePB = (b * H + yp) * rowB;

        DescO o;
        o.x = baseB  + x0 * (C_ * 4);
        o.y = baseB  + xp * (C_ * 4);
        o.z = basePB + x0 * (C_ * 4);
        o.w = basePB + xp * (C_ * 4);
        cdo[t] = o;

        float omwx = 1.0f - wx;
        float omwy = 1.0f - wy;
        DescW w;
        w.w00 = omwx * omwy * validf;
        w.w01 = wx   * omwy * validf;
        w.w10 = omwx * wy   * validf;
        w.w11 = wx   * wy   * validf;
        cdw[t] = w;
    }
    __syncthreads();

    // thread t owns channel t: each warp-LDG covers exactly one 128B line
    const char* fbase = (const char*)(s_lvl ? feat1 : feat0) + t * 4;
    float* outbase = out + (size_t)n * NCELLB_ * C_ + t;

    #pragma unroll 7
    for (int cell = 0; cell < NCELLB_; cell++) {
        DescO o = cdo[cell];
        float a = __ldg((const float*)(fbase + o.x));
        float c = __ldg((const float*)(fbase + o.y));
        float e = __ldg((const float*)(fbase + o.z));
        float f = __ldg((const float*)(fbase + o.w));

        DescW w = cdw[cell];
        float r = a * w.w00;
        r = fmaf(c, w.w01, r);
        r = fmaf(e, w.w10, r);
        r = fmaf(f, w.w11, r);

        __stcs(outbase + cell * C_, r);
    }
}

extern "C" void kernel_launch(void* const* d_in, const int* in_sizes, int n_in,
                              void* d_out, int out_size)
{
    const float* feat0 = (const float*)d_in[0];
    const float* feat1 = (const float*)d_in[1];
    const float* rois  = (const float*)d_in[2];
    float* out = (float*)d_out;

    roialign_kernel<<<NBOX_, THREADS_>>>(feat0, feat1, rois, out);
}

// round 11
// speedup vs baseline: 1.3283x; 1.3283x over previous
#include <cuda_runtime.h>
#include <cstdint>

#define B_     2
#define R_     512
#define C_     256
#define H0_    256
#define H1_    128
#define NBOX_  (B_ * R_)            // 1024
#define NCELLB_ 49
#define NPAD_  56                   // 8 lanes x 7 iterations
#define CG_    (C_ / 4)             // 64 float4 groups per pixel
#define THREADS_ 512                // 64 cgroups x 8 cell-lanes

typedef unsigned long long u64;

struct Desc {                // 48 bytes
    int4 o;                  // byte offsets of 4 corners
    ulonglong2 wA;           // packed f32x2: {w00,w00}, {w01,w01}
    ulonglong2 wB;           // packed f32x2: {w10,w10}, {w11,w11}
};

__device__ __forceinline__ u64 fma2(u64 a, u64 b, u64 c) {
    u64 d;
    asm("fma.rn.f32x2 %0, %1, %2, %3;" : "=l"(d) : "l"(a), "l"(b), "l"(c));
    return d;
}
__device__ __forceinline__ u64 mul2(u64 a, u64 b) {
    u64 d;
    asm("mul.rn.f32x2 %0, %1, %2;" : "=l"(d) : "l"(a), "l"(b));
    return d;
}
__device__ __forceinline__ u64 bcast2(float w) {
    return (u64)__float_as_uint(w) * 0x100000001ULL;
}

__global__ __launch_bounds__(THREADS_, 4) void roialign_kernel(
    const float* __restrict__ feat0,
    const float* __restrict__ feat1,
    const float* __restrict__ rois,
    float* __restrict__ out)
{
    __shared__ Desc cd[NPAD_];
    __shared__ int s_lvl;

    int n = blockIdx.x;
    int t = threadIdx.x;

    if (t < NPAD_) {
        Desc d;
        d.o = make_int4(0, 0, 0, 0);
        d.wA.x = 0; d.wA.y = 0; d.wB.x = 0; d.wB.y = 0;
        if (t < NCELLB_) {
            const float* roi = rois + (size_t)n * 5;
            float y1 = roi[0], x1 = roi[1], y2 = roi[2], x2 = roi[3];
            bool lvl = ((y2 - y1) > 48.0f) || ((x2 - x1) > 48.0f);
            if (t == 0) s_lvl = lvl ? 1 : 0;
            int H = lvl ? H1_ : H0_;
            float Hm1 = (float)(H - 1);
            int b = n >> 9;

            const float inv = 1.0f / 1024.0f;
            float y1n = y1 * inv, x1n = x1 * inv, y2n = y2 * inv, x2n = x2 * inv;

            int py = t / 7;
            int px = t - py * 7;
            float ry = (float)py * (1.0f / 6.0f);
            float rx = (float)px * (1.0f / 6.0f);
            float ys = (y1n + ry * (y2n - y1n)) * Hm1;
            float xs = (x1n + rx * (x2n - x1n)) * Hm1;

            float validf = ((ys >= 0.0f) && (ys <= Hm1) && (xs >= 0.0f) && (xs <= Hm1))
                           ? 1.0f : 0.0f;

            float y0f = floorf(ys);
            float x0f = floorf(xs);
            float wy = ys - y0f;
            float wx = xs - x0f;
            int y0 = (int)fminf(fmaxf(y0f, 0.0f), Hm1);
            int x0 = (int)fminf(fmaxf(x0f, 0.0f), Hm1);
            int yp = min(y0 + 1, H - 1);
            int xp = min(x0 + 1, H - 1);

            int rowB = H * (C_ * 4);
            int baseB  = (b * H + y0) * rowB;
            int basePB = (b * H + yp) * rowB;

            d.o.x = baseB  + x0 * (C_ * 4);
            d.o.y = baseB  + xp * (C_ * 4);
            d.o.z = basePB + x0 * (C_ * 4);
            d.o.w = basePB + xp * (C_ * 4);

            float omwx = 1.0f - wx;
            float omwy = 1.0f - wy;
            d.wA.x = bcast2(omwx * omwy * validf);
            d.wA.y = bcast2(wx   * omwy * validf);
            d.wB.x = bcast2(omwx * wy   * validf);
            d.wB.y = bcast2(wx   * wy   * validf);
        }
        cd[t] = d;
    }
    __syncthreads();

    int cg   = t & (CG_ - 1);        // channel group 0..63
    int lane = t >> 6;               // cell lane 0..7 (full pool row +1 in flight)

    const char* fbase = (const char*)(s_lvl ? feat1 : feat0) + cg * 16;
    longlong2* outbase = (longlong2*)out + (size_t)n * NCELLB_ * (C_ / 4) + cg;

    #pragma unroll
    for (int i = 0; i < 7; i++) {
        int cell = lane + i * 8;
        Desc d = cd[cell];
        ulonglong2 a = __ldg((const ulonglong2*)(fbase + d.o.x));
        ulonglong2 c = __ldg((const ulonglong2*)(fbase + d.o.y));
        ulonglong2 e = __ldg((const ulonglong2*)(fbase + d.o.z));
        ulonglong2 f = __ldg((const ulonglong2*)(fbase + d.o.w));

        ulonglong2 r;
        r.x = fma2(f.x, d.wB.y, fma2(e.x, d.wB.x, fma2(c.x, d.wA.y, mul2(a.x, d.wA.x))));
        r.y = fma2(f.y, d.wB.y, fma2(e.y, d.wB.x, fma2(c.y, d.wA.y, mul2(a.y, d.wA.x))));

        if (cell < NCELLB_) {
            longlong2 rs;
            rs.x = (long long)r.x;
            rs.y = (long long)r.y;
            __stcs(outbase + cell * (C_ / 4), rs);
        }
    }
}

extern "C" void kernel_launch(void* const* d_in, const int* in_sizes, int n_in,
                              void* d_out, int out_size)
{
    const float* feat0 = (const float*)d_in[0];
    const float* feat1 = (const float*)d_in[1];
    const float* rois  = (const float*)d_in[2];
    float* out = (float*)d_out;

    roialign_kernel<<<NBOX_, THREADS_>>>(feat0, feat1, rois, out);
}